// round 14
// baseline (speedup 1.0000x reference)
#include <cuda_runtime.h>
#include <cuda_fp16.h>
#include <cstdint>

#define N_NODES 50000
#define N_EDGES 800000
#define N_GRAPHS 128
#define D 128
#define L 4
#define C 10
#define GN_EPS 1e-5f
#define NB_SCAN 196
#define PAD 132          // float padding (stats staging)
#define PADH 136         // half padding (GEMM tiles), 68 words/row
#define ZERO_ELEMS (L * N_GRAPHS * 2 * D)
#define GIN_TILES 391    // ceil(N_NODES/128)
#define GIN_GRID 296     // 148 SMs x 2 guaranteed-resident CTAs

// ------------------------- device scratch (static, no allocs) -------------
__device__ __half g_h16[(size_t)N_NODES * D]; // un-normalized H (fp16)
__device__ __half g_hh[(size_t)N_NODES * D];  // fp16 normalized state
__device__ int    g_rowptr[N_NODES + 1];
__device__ int    g_cursor[N_NODES];
__device__ int    g_cnt[N_NODES];
__device__ int    g_col[N_EDGES];
__device__ int    g_gptr[N_GRAPHS + 1];
__device__ float  g_gcnt[N_GRAPHS];
__device__ float  g_pool[N_GRAPHS * D];
__device__ float  g_stat[L][N_GRAPHS][2][D];
__device__ __half g_wTh[8][16384];            // W^T fp16, B[n][k]
__device__ int    g_bar[L];                   // grid barrier counters
__device__ int    g_is64e;
__device__ int    g_is64b;

// ------------------------- helpers ----------------------------------------
__device__ __forceinline__ int e_at(const void* p, long long i) {
    if (g_is64e) return (int)((const long long*)p)[i];
    return ((const int*)p)[i];
}
__device__ __forceinline__ int b_at(const void* p, long long i) {
    if (g_is64b) return (int)((const long long*)p)[i];
    return ((const int*)p)[i];
}

// mma.sync m16n8k16 fp16 (fp32 accum): C += A*B
__device__ __forceinline__ void mma_f16(float c[4], uint32_t a0, uint32_t a1,
                                        uint32_t a2, uint32_t a3,
                                        uint32_t b0, uint32_t b1) {
    asm volatile(
        "mma.sync.aligned.m16n8k16.row.col.f32.f16.f16.f32 "
        "{%0,%1,%2,%3}, {%4,%5,%6,%7}, {%8,%9}, {%0,%1,%2,%3};"
        : "+f"(c[0]), "+f"(c[1]), "+f"(c[2]), "+f"(c[3])
        : "r"(a0), "r"(a1), "r"(a2), "r"(a3), "r"(b0), "r"(b1));
}

__device__ __forceinline__ void acc_h4(float4& acc, uint2 r) {
    float2 f0 = __half22float2(*reinterpret_cast<__half2*>(&r.x));
    float2 f1 = __half22float2(*reinterpret_cast<__half2*>(&r.y));
    acc.x += f0.x; acc.y += f0.y; acc.z += f1.x; acc.w += f1.y;
}
__device__ __forceinline__ uint32_t pack_h2(float x, float y) {
    __half2 h = __floats2half2_rn(x, y);
    return *reinterpret_cast<uint32_t*>(&h);
}

// --------- fused prologue: zero + detect + graphs + wT + x mirror ----------
__global__ void k_prep(const int* __restrict__ ew, const int* __restrict__ bw,
                       const float* __restrict__ w1, const float* __restrict__ w2,
                       const float* __restrict__ x) {
    int gsz = gridDim.x * blockDim.x;
    int gid0 = blockIdx.x * blockDim.x + threadIdx.x;

    if (blockIdx.x == 0) {
        __shared__ int s_ez, s_bg;
        if (threadIdx.x == 0) { s_ez = 1; s_bg = 0; }
        __syncthreads();
        for (int j = threadIdx.x; j < 128; j += blockDim.x)
            if (ew[2 * j + 1] != 0) atomicAnd(&s_ez, 0);
        for (int j = threadIdx.x; j < 24999; j += blockDim.x)
            if (bw[2 * j] > bw[2 * j + 1]) atomicOr(&s_bg, 1);
        __syncthreads();
        if (threadIdx.x == 0) {
            g_is64e = s_ez; g_is64b = s_bg;
            for (int l = 0; l < L; l++) g_bar[l] = 0;
        }
        if (threadIdx.x < N_GRAPHS) {
            int g = threadIdx.x;
            int lo = 0, hi = N_NODES;
            while (lo < hi) {
                int mid = (lo + hi) >> 1;
                int v = s_bg ? (int)((const long long*)bw)[mid] : bw[mid];
                if (v < g) lo = mid + 1; else hi = mid;
            }
            g_gptr[g] = lo;
            if (g == 0) g_gptr[N_GRAPHS] = N_NODES;
        }
        __syncthreads();
        if (threadIdx.x < N_GRAPHS) {
            int g = threadIdx.x;
            int nxt = (g < N_GRAPHS - 1) ? g_gptr[g + 1] : N_NODES;
            g_gcnt[g] = fmaxf((float)(nxt - g_gptr[g]), 1.0f);
        }
    }

    for (int i = gid0; i < ZERO_ELEMS; i += gsz) {
        if (i < N_NODES) g_cnt[i] = 0;
        (&g_stat[0][0][0][0])[i] = 0.f;
        if (i < N_GRAPHS * D) g_pool[i] = 0.f;
    }
    for (int i = gid0; i < 8 * 16384; i += gsz) {
        int m = i >> 14, idx = i & 16383;
        int k = idx >> 7, n = idx & 127;
        const float* W = (m < 4) ? (w1 + (size_t)m * D * D)
                                 : (w2 + (size_t)(m - 4) * D * D);
        g_wTh[m][n * D + k] = __float2half(W[idx]);
    }
    for (int i = gid0; i < N_NODES * D / 4; i += gsz) {
        float4 v = *(const float4*)(x + (size_t)i * 4);
        uint2 pk;
        pk.x = pack_h2(v.x, v.y);
        pk.y = pack_h2(v.z, v.w);
        ((uint2*)g_hh)[i] = pk;
    }
}

// ------------------------- CSR build ---------------------------------------
__global__ void k_hist(const void* __restrict__ e) {
    int i = blockIdx.x * blockDim.x + threadIdx.x;
    if (i < N_EDGES) atomicAdd(&g_cnt[e_at(e, (long long)N_EDGES + i)], 1);
}

__global__ void k_scan() {
    __shared__ int red[256];
    int t = threadIdx.x, b = blockIdx.x;
    int idx = b * 256 + t;

    int base = 0;
    for (int i = t; i < b * 256; i += 256) base += g_cnt[i];
    red[t] = base;
    __syncthreads();
    for (int off = 128; off > 0; off >>= 1) {
        if (t < off) red[t] += red[t + off];
        __syncthreads();
    }
    int blockBase = red[0];
    __syncthreads();

    int v = (idx < N_NODES) ? g_cnt[idx] : 0;
    red[t] = v;
    __syncthreads();
    for (int off = 1; off < 256; off <<= 1) {
        int u = (t >= off) ? red[t - off] : 0;
        __syncthreads(); red[t] += u; __syncthreads();
    }
    if (idx < N_NODES) {
        int rp = blockBase + red[t] - v;
        g_rowptr[idx] = rp; g_cursor[idx] = rp;
    }
    if (b == NB_SCAN - 1 && t == 255) g_rowptr[N_NODES] = blockBase + red[255];
}

__global__ void k_fill(const void* __restrict__ e) {
    int i = blockIdx.x * blockDim.x + threadIdx.x;
    if (i < N_EDGES) {
        int s = e_at(e, i);
        int d = e_at(e, (long long)N_EDGES + i);
        g_col[atomicAdd(&g_cursor[d], 1)] = s;
    }
}

// ---- persistent fused GIN layer: gather + 2xGEMM + stats + GraphNorm ------
// 296 CTAs, __launch_bounds__(512,2) => provably all resident => the software
// grid barrier is deadlock-free. Tile t's gathered rows are consumed only by
// the CTA that gathers them (smem-local), so no barrier before the GEMMs;
// g_hh for this layer was fully written by the PREVIOUS launch (cross-launch
// ordering), so the gather is race-free.
#define SMEM_GIN ((128 * PADH + 128 * PADH) * 2)

__global__ void __launch_bounds__(512, 2) k_gin(int layer,
                                                const float* __restrict__ bias1,
                                                const float* __restrict__ bias2,
                                                const void* __restrict__ batch,
                                                const float* __restrict__ gnw,
                                                const float* __restrict__ gnb,
                                                const float* __restrict__ gns,
                                                int last) {
    extern __shared__ __half smh[];
    __half* As = smh;                    // [128][PADH]
    __half* Bs = smh + 128 * PADH;       // [128][PADH]
    uint32_t* As32 = (uint32_t*)As;
    uint32_t* Bs32 = (uint32_t*)Bs;
    __shared__ float b1s[128], b2s[128];
    __shared__ int gids[128];

    int tid = threadIdx.x, lane = tid & 31, wid = tid >> 5;
    int warp_m = wid & 3, warp_n = wid >> 2;     // 4 x 4 warp grid, 32x32 tiles
    int gID = lane >> 2, tig = lane & 3;

    // ---------------- phase 1: gather + GEMMs + stats per tile -------------
    for (int t = blockIdx.x; t < GIN_TILES; t += GIN_GRID) {
        int rb = t * 128;
        int nvalid = min(128, N_NODES - rb);

        // fused edge gather directly into As: warp w rows w, w+16, ...
        for (int rr = wid; rr < 128; rr += 16) {
            int gr = rb + rr;
            float4 acc = make_float4(0.f, 0.f, 0.f, 0.f);
            if (gr < N_NODES) {
                acc_h4(acc, __ldg(((const uint2*)(g_hh + (size_t)gr * D)) + lane));
                int s = g_rowptr[gr], e = g_rowptr[gr + 1];
                int i = s;
                for (; i + 4 <= e; i += 4) {
                    int s0 = g_col[i], s1 = g_col[i + 1];
                    int s2 = g_col[i + 2], s3 = g_col[i + 3];
                    uint2 r0 = __ldg(((const uint2*)(g_hh + (size_t)s0 * D)) + lane);
                    uint2 r1 = __ldg(((const uint2*)(g_hh + (size_t)s1 * D)) + lane);
                    uint2 r2 = __ldg(((const uint2*)(g_hh + (size_t)s2 * D)) + lane);
                    uint2 r3 = __ldg(((const uint2*)(g_hh + (size_t)s3 * D)) + lane);
                    acc_h4(acc, r0); acc_h4(acc, r1);
                    acc_h4(acc, r2); acc_h4(acc, r3);
                }
                for (; i < e; i++)
                    acc_h4(acc, __ldg(((const uint2*)(g_hh + (size_t)g_col[i] * D)) + lane));
            }
            uint2 pk;
            pk.x = pack_h2(acc.x, acc.y);
            pk.y = pack_h2(acc.z, acc.w);
            *(uint2*)(As32 + rr * 68 + lane * 2) = pk;
        }
#pragma unroll
        for (int it = 0; it < 4; it++) {          // stage W1^T
            int idx = tid + it * 512;
            int r = idx >> 4, c8 = (idx & 15) * 8;
            *(uint4*)(Bs + r * PADH + c8) = *(const uint4*)(g_wTh[layer] + r * D + c8);
        }
        if (tid < 128) b1s[tid] = bias1[tid];
        else if (tid < 256) b2s[tid - 128] = bias2[tid - 128];
        else if (tid < 384) {
            int r = tid - 256;
            gids[r] = (r < nvalid) ? b_at(batch, rb + r) : 0;
        }
        __syncthreads();

        float c[2][4][4];
#pragma unroll
        for (int i = 0; i < 2; i++)
#pragma unroll
            for (int j = 0; j < 4; j++)
#pragma unroll
                for (int q = 0; q < 4; q++) c[i][j][q] = 0.f;

        // GEMM1
#pragma unroll
        for (int kk = 0; kk < 8; kk++) {
            int kw = kk * 8 + tig;
            uint32_t a[2][4];
#pragma unroll
            for (int i = 0; i < 2; i++) {
                int r0 = (warp_m * 32 + i * 16 + gID) * 68;
                a[i][0] = As32[r0 + kw];
                a[i][1] = As32[r0 + 8 * 68 + kw];
                a[i][2] = As32[r0 + kw + 4];
                a[i][3] = As32[r0 + 8 * 68 + kw + 4];
            }
#pragma unroll
            for (int j = 0; j < 4; j++) {
                int n = warp_n * 32 + j * 8 + gID;
                uint32_t b0 = Bs32[n * 68 + kw];
                uint32_t b1 = Bs32[n * 68 + kw + 4];
                mma_f16(c[0][j], a[0][0], a[0][1], a[0][2], a[0][3], b0, b1);
                mma_f16(c[1][j], a[1][0], a[1][1], a[1][2], a[1][3], b0, b1);
            }
        }
        __syncthreads();

        // H1 -> As, stage W2^T -> Bs
#pragma unroll
        for (int i = 0; i < 2; i++) {
            int r0 = warp_m * 32 + i * 16 + gID;
#pragma unroll
            for (int j = 0; j < 4; j++) {
                int cb = warp_n * 32 + j * 8 + 2 * tig;
                int w = warp_n * 16 + j * 4 + tig;
                As32[r0 * 68 + w] =
                    pack_h2(fmaxf(c[i][j][0] + b1s[cb], 0.f),
                            fmaxf(c[i][j][1] + b1s[cb + 1], 0.f));
                As32[(r0 + 8) * 68 + w] =
                    pack_h2(fmaxf(c[i][j][2] + b1s[cb], 0.f),
                            fmaxf(c[i][j][3] + b1s[cb + 1], 0.f));
            }
        }
#pragma unroll
        for (int it = 0; it < 4; it++) {
            int idx = tid + it * 512;
            int r = idx >> 4, c8 = (idx & 15) * 8;
            *(uint4*)(Bs + r * PADH + c8) = *(const uint4*)(g_wTh[4 + layer] + r * D + c8);
        }
        __syncthreads();

        // GEMM2
#pragma unroll
        for (int i = 0; i < 2; i++)
#pragma unroll
            for (int j = 0; j < 4; j++)
#pragma unroll
                for (int q = 0; q < 4; q++) c[i][j][q] = 0.f;

#pragma unroll
        for (int kk = 0; kk < 8; kk++) {
            int kw = kk * 8 + tig;
            uint32_t a[2][4];
#pragma unroll
            for (int i = 0; i < 2; i++) {
                int r0 = (warp_m * 32 + i * 16 + gID) * 68;
                a[i][0] = As32[r0 + kw];
                a[i][1] = As32[r0 + 8 * 68 + kw];
                a[i][2] = As32[r0 + kw + 4];
                a[i][3] = As32[r0 + 8 * 68 + kw + 4];
            }
#pragma unroll
            for (int j = 0; j < 4; j++) {
                int n = warp_n * 32 + j * 8 + gID;
                uint32_t b0 = Bs32[n * 68 + kw];
                uint32_t b1 = Bs32[n * 68 + kw + 4];
                mma_f16(c[0][j], a[0][0], a[0][1], a[0][2], a[0][3], b0, b1);
                mma_f16(c[1][j], a[1][0], a[1][1], a[1][2], a[1][3], b0, b1);
            }
        }
        __syncthreads();

        // epilogue: H -> g_h16 + smem float staging for stats
        float* Hs = (float*)smh;
#pragma unroll
        for (int i = 0; i < 2; i++) {
            int lr0 = warp_m * 32 + i * 16 + gID;
            int lr1 = lr0 + 8;
#pragma unroll
            for (int j = 0; j < 4; j++) {
                int cb = warp_n * 32 + j * 8 + 2 * tig;
                float o00 = fmaxf(c[i][j][0] + b2s[cb], 0.f);
                float o01 = fmaxf(c[i][j][1] + b2s[cb + 1], 0.f);
                float o10 = fmaxf(c[i][j][2] + b2s[cb], 0.f);
                float o11 = fmaxf(c[i][j][3] + b2s[cb + 1], 0.f);
                Hs[lr0 * PAD + cb] = o00;  Hs[lr0 * PAD + cb + 1] = o01;
                Hs[lr1 * PAD + cb] = o10;  Hs[lr1 * PAD + cb + 1] = o11;
                if (lr0 < nvalid)
                    *(uint32_t*)(g_h16 + (size_t)(rb + lr0) * D + cb) = pack_h2(o00, o01);
                if (lr1 < nvalid)
                    *(uint32_t*)(g_h16 + (size_t)(rb + lr1) * D + cb) = pack_h2(o10, o11);
            }
        }
        __syncthreads();

        // per-graph stats
        {
            int d = tid & 127, strip = tid >> 7;
            int r0 = strip * 32, r1 = min(r0 + 32, nvalid);
            if (r0 < nvalid) {
                int curg = gids[r0];
                float s = 0.f, q = 0.f;
                for (int r = r0; r < r1; r++) {
                    int g = gids[r];
                    if (g != curg) {
                        atomicAdd(&g_stat[layer][curg][0][d], s);
                        atomicAdd(&g_stat[layer][curg][1][d], q);
                        s = 0.f; q = 0.f; curg = g;
                    }
                    float v = Hs[r * PAD + d];
                    s += v; q += v * v;
                }
                atomicAdd(&g_stat[layer][curg][0][d], s);
                atomicAdd(&g_stat[layer][curg][1][d], q);
            }
        }
        __syncthreads();   // before next tile overwrites smem
    }

    // ---------------- grid barrier (deadlock-free: all CTAs resident) ------
    __threadfence();
    __syncthreads();
    if (tid == 0) {
        atomicAdd(&g_bar[layer], 1);
        while (atomicAdd(&g_bar[layer], 0) < GIN_GRID)
            __nanosleep(64);
    }
    __syncthreads();
    __threadfence();

    // ---------------- phase 2: GraphNorm apply on own tiles ----------------
    for (int t = blockIdx.x; t < GIN_TILES; t += GIN_GRID) {
        int rb = t * 128;
        int nvalid = min(128, N_NODES - rb);
        for (int rr = wid; rr < nvalid; rr += 16) {
            int r = rb + rr;
            int g = b_at(batch, r);
            float cgc = g_gcnt[g];
            int d0 = lane * 4;
            uint2 hr = ((const uint2*)(g_h16 + (size_t)r * D))[lane];
            float2 hf0 = __half22float2(*reinterpret_cast<__half2*>(&hr.x));
            float2 hf1 = __half22float2(*reinterpret_cast<__half2*>(&hr.y));
            float4 h = make_float4(hf0.x, hf0.y, hf1.x, hf1.y);
            float4 s4 = *(const float4*)&g_stat[layer][g][0][d0];
            float4 q4 = *(const float4*)&g_stat[layer][g][1][d0];
            float4 ms4 = *(const float4*)(gns + layer * D + d0);
            float4 w4  = *(const float4*)(gnw + layer * D + d0);
            float4 b4  = *(const float4*)(gnb + layer * D + d0);
            float4 o;
#define GN1(X) {                                                   \
    float mean = s4.X / cgc;                                       \
    float aa = mean * ms4.X;                                       \
    float var = q4.X / cgc - 2.f * aa * mean + aa * aa;            \
    float rstd = rsqrtf(var + GN_EPS);                             \
    o.X = fmaxf(w4.X * (h.X - aa) * rstd + b4.X, 0.f); }
            GN1(x) GN1(y) GN1(z) GN1(w)
#undef GN1
            if (last) {
                atomicAdd(&g_pool[g * D + d0 + 0], o.x);
                atomicAdd(&g_pool[g * D + d0 + 1], o.y);
                atomicAdd(&g_pool[g * D + d0 + 2], o.z);
                atomicAdd(&g_pool[g * D + d0 + 3], o.w);
            } else {
                uint2 pk;
                pk.x = pack_h2(o.x, o.y);
                pk.y = pack_h2(o.z, o.w);
                ((uint2*)(g_hh + (size_t)r * D))[lane] = pk;
            }
        }
    }
}

// ------------------------- final MLP + log_softmax -------------------------
__global__ void __launch_bounds__(128) k_mlp(const float* __restrict__ fw1,
                                             const float* __restrict__ fb1,
                                             const float* __restrict__ fw2,
                                             const float* __restrict__ fb2,
                                             const float* __restrict__ fw3,
                                             const float* __restrict__ fb3,
                                             float* __restrict__ out) {
    int g = blockIdx.x, t = threadIdx.x;
    __shared__ float v[D], v2[D], o[C], red[2];
    v[t] = g_pool[g * D + t];
    __syncthreads();
    float acc = fb1[t];
    for (int k = 0; k < D; k++) acc += v[k] * fw1[k * D + t];
    v2[t] = fmaxf(acc, 0.f);
    __syncthreads();
    acc = fb2[t];
    for (int k = 0; k < D; k++) acc += v2[k] * fw2[k * D + t];
    __syncthreads();
    v[t] = fmaxf(acc, 0.f);
    __syncthreads();
    if (t < C) {
        float a = fb3[t];
        for (int k = 0; k < D; k++) a += v[k] * fw3[k * C + t];
        o[t] = a;
    }
    __syncthreads();
    if (t == 0) {
        float m = -1e30f;
        for (int cc = 0; cc < C; cc++) m = fmaxf(m, o[cc]);
        float se = 0.f;
        for (int cc = 0; cc < C; cc++) se += expf(o[cc] - m);
        red[0] = m; red[1] = logf(se);
    }
    __syncthreads();
    if (t < C) out[g * C + t] = o[t] - red[0] - red[1];
}

// ------------------------- launcher ----------------------------------------
extern "C" void kernel_launch(void* const* d_in, const int* in_sizes, int n_in,
                              void* d_out, int out_size) {
    const float* x    = (const float*)d_in[0];
    const float* w1   = (const float*)d_in[1];
    const float* b1   = (const float*)d_in[2];
    const float* w2   = (const float*)d_in[3];
    const float* b2   = (const float*)d_in[4];
    const float* gnw  = (const float*)d_in[5];
    const float* gnb  = (const float*)d_in[6];
    const float* gns  = (const float*)d_in[7];
    const float* fw1  = (const float*)d_in[8];
    const float* fb1  = (const float*)d_in[9];
    const float* fw2  = (const float*)d_in[10];
    const float* fb2  = (const float*)d_in[11];
    const float* fw3  = (const float*)d_in[12];
    const float* fb3  = (const float*)d_in[13];
    const void*  edge  = d_in[14];
    const void*  batch = d_in[15];
    float* out = (float*)d_out;

    cudaFuncSetAttribute(k_gin, cudaFuncAttributeMaxDynamicSharedMemorySize,
                         SMEM_GIN);

    // prologue: fused prep, then CSR build
    k_prep<<<1024, 256>>>((const int*)edge, (const int*)batch, w1, w2, x);
    k_hist<<<(N_EDGES + 255) / 256, 256>>>(edge);
    k_scan<<<NB_SCAN, 256>>>();
    k_fill<<<(N_EDGES + 255) / 256, 256>>>(edge);

    for (int l = 0; l < L; l++) {
        k_gin<<<GIN_GRID, 512, SMEM_GIN>>>(l,         // gather+gemm+norm
                                           b1 + (size_t)l * D, b2 + (size_t)l * D,
                                           batch, gnw, gnb, gns, l == L - 1);
    }
    k_mlp<<<N_GRAPHS, 128>>>(fw1, fb1, fw2, fb2, fw3, fb3, out);
}

// round 15
// speedup vs baseline: 1.1192x; 1.1192x over previous
#include <cuda_runtime.h>
#include <cuda_fp16.h>
#include <cstdint>

#define N_NODES 50000
#define N_EDGES 800000
#define N_GRAPHS 128
#define D 128
#define L 4
#define C 10
#define GN_EPS 1e-5f
#define NB_SCAN 196
#define PADH 136         // half padding (tiles), 68 words/row
#define ZERO_ELEMS (L * N_GRAPHS * 2 * D)
#define GIN_TILES 391    // ceil(N_NODES/128)
#define GIN_GRID 296     // 148 SMs x 2 guaranteed-resident CTAs

// ------------------------- device scratch (static, no allocs) -------------
__device__ __half g_h16[(size_t)N_NODES * D]; // un-normalized H (fp16)
__device__ __half g_ah[(size_t)N_NODES * D];  // agg output (fp16, gin input)
__device__ __half g_hh[(size_t)N_NODES * D];  // fp16 normalized state
__device__ int    g_rowptr[N_NODES + 1];
__device__ int    g_cursor[N_NODES];
__device__ int    g_cnt[N_NODES];
__device__ int    g_col[N_EDGES];
__device__ int    g_gptr[N_GRAPHS + 1];
__device__ float  g_gcnt[N_GRAPHS];
__device__ float  g_pool[N_GRAPHS * D];
__device__ float  g_stat[L][N_GRAPHS][2][D];
__device__ __half g_wTh[8][16384];            // W^T fp16, B[n][k]
__device__ int    g_bar[L];                   // grid barrier counters
__device__ int    g_is64e;
__device__ int    g_is64b;

// ------------------------- helpers ----------------------------------------
__device__ __forceinline__ int e_at(const void* p, long long i) {
    if (g_is64e) return (int)((const long long*)p)[i];
    return ((const int*)p)[i];
}
__device__ __forceinline__ int b_at(const void* p, long long i) {
    if (g_is64b) return (int)((const long long*)p)[i];
    return ((const int*)p)[i];
}

// mma.sync m16n8k16 fp16 (fp32 accum): C += A*B
__device__ __forceinline__ void mma_f16(float c[4], uint32_t a0, uint32_t a1,
                                        uint32_t a2, uint32_t a3,
                                        uint32_t b0, uint32_t b1) {
    asm volatile(
        "mma.sync.aligned.m16n8k16.row.col.f32.f16.f16.f32 "
        "{%0,%1,%2,%3}, {%4,%5,%6,%7}, {%8,%9}, {%0,%1,%2,%3};"
        : "+f"(c[0]), "+f"(c[1]), "+f"(c[2]), "+f"(c[3])
        : "r"(a0), "r"(a1), "r"(a2), "r"(a3), "r"(b0), "r"(b1));
}

__device__ __forceinline__ void acc_h4(float4& acc, uint2 r) {
    float2 f0 = __half22float2(*reinterpret_cast<__half2*>(&r.x));
    float2 f1 = __half22float2(*reinterpret_cast<__half2*>(&r.y));
    acc.x += f0.x; acc.y += f0.y; acc.z += f1.x; acc.w += f1.y;
}
__device__ __forceinline__ uint32_t pack_h2(float x, float y) {
    __half2 h = __floats2half2_rn(x, y);
    return *reinterpret_cast<uint32_t*>(&h);
}

// --------- fused prologue: zero + detect + graphs + wT + x mirror ----------
__global__ void k_prep(const int* __restrict__ ew, const int* __restrict__ bw,
                       const float* __restrict__ w1, const float* __restrict__ w2,
                       const float* __restrict__ x) {
    int gsz = gridDim.x * blockDim.x;
    int gid0 = blockIdx.x * blockDim.x + threadIdx.x;

    if (blockIdx.x == 0) {
        __shared__ int s_ez, s_bg;
        if (threadIdx.x == 0) { s_ez = 1; s_bg = 0; }
        __syncthreads();
        for (int j = threadIdx.x; j < 128; j += blockDim.x)
            if (ew[2 * j + 1] != 0) atomicAnd(&s_ez, 0);
        for (int j = threadIdx.x; j < 24999; j += blockDim.x)
            if (bw[2 * j] > bw[2 * j + 1]) atomicOr(&s_bg, 1);
        __syncthreads();
        if (threadIdx.x == 0) {
            g_is64e = s_ez; g_is64b = s_bg;
            for (int l = 0; l < L; l++) g_bar[l] = 0;
        }
        if (threadIdx.x < N_GRAPHS) {
            int g = threadIdx.x;
            int lo = 0, hi = N_NODES;
            while (lo < hi) {
                int mid = (lo + hi) >> 1;
                int v = s_bg ? (int)((const long long*)bw)[mid] : bw[mid];
                if (v < g) lo = mid + 1; else hi = mid;
            }
            g_gptr[g] = lo;
            if (g == 0) g_gptr[N_GRAPHS] = N_NODES;
        }
        __syncthreads();
        if (threadIdx.x < N_GRAPHS) {
            int g = threadIdx.x;
            int nxt = (g < N_GRAPHS - 1) ? g_gptr[g + 1] : N_NODES;
            g_gcnt[g] = fmaxf((float)(nxt - g_gptr[g]), 1.0f);
        }
    }

    for (int i = gid0; i < ZERO_ELEMS; i += gsz) {
        if (i < N_NODES) g_cnt[i] = 0;
        (&g_stat[0][0][0][0])[i] = 0.f;
        if (i < N_GRAPHS * D) g_pool[i] = 0.f;
    }
    for (int i = gid0; i < 8 * 16384; i += gsz) {
        int m = i >> 14, idx = i & 16383;
        int k = idx >> 7, n = idx & 127;
        const float* W = (m < 4) ? (w1 + (size_t)m * D * D)
                                 : (w2 + (size_t)(m - 4) * D * D);
        g_wTh[m][n * D + k] = __float2half(W[idx]);
    }
    for (int i = gid0; i < N_NODES * D / 4; i += gsz) {
        float4 v = *(const float4*)(x + (size_t)i * 4);
        uint2 pk;
        pk.x = pack_h2(v.x, v.y);
        pk.y = pack_h2(v.z, v.w);
        ((uint2*)g_hh)[i] = pk;
    }
}

// ------------------------- CSR build ---------------------------------------
__global__ void k_hist(const void* __restrict__ e) {
    int i = blockIdx.x * blockDim.x + threadIdx.x;
    if (i < N_EDGES) atomicAdd(&g_cnt[e_at(e, (long long)N_EDGES + i)], 1);
}

__global__ void k_scan() {
    __shared__ int red[256];
    int t = threadIdx.x, b = blockIdx.x;
    int idx = b * 256 + t;

    int base = 0;
    for (int i = t; i < b * 256; i += 256) base += g_cnt[i];
    red[t] = base;
    __syncthreads();
    for (int off = 128; off > 0; off >>= 1) {
        if (t < off) red[t] += red[t + off];
        __syncthreads();
    }
    int blockBase = red[0];
    __syncthreads();

    int v = (idx < N_NODES) ? g_cnt[idx] : 0;
    red[t] = v;
    __syncthreads();
    for (int off = 1; off < 256; off <<= 1) {
        int u = (t >= off) ? red[t - off] : 0;
        __syncthreads(); red[t] += u; __syncthreads();
    }
    if (idx < N_NODES) {
        int rp = blockBase + red[t] - v;
        g_rowptr[idx] = rp; g_cursor[idx] = rp;
    }
    if (b == NB_SCAN - 1 && t == 255) g_rowptr[N_NODES] = blockBase + red[255];
}

__global__ void k_fill(const void* __restrict__ e) {
    int i = blockIdx.x * blockDim.x + threadIdx.x;
    if (i < N_EDGES) {
        int s = e_at(e, i);
        int d = e_at(e, (long long)N_EDGES + i);
        g_col[atomicAdd(&g_cursor[d], 1)] = s;
    }
}

// ------------------------- aggregation (fp16 in, fp16 out) -----------------
// Standalone high-parallelism gather (R14 lesson: do NOT fuse into gin).
__global__ void __launch_bounds__(256) k_agg() {
    int warp = (blockIdx.x * blockDim.x + threadIdx.x) >> 5;
    int lane = threadIdx.x & 31;
    if (warp >= N_NODES) return;
    int s = g_rowptr[warp], e = g_rowptr[warp + 1];
    float4 acc = make_float4(0.f, 0.f, 0.f, 0.f);
    acc_h4(acc, __ldg(((const uint2*)(g_hh + (size_t)warp * D)) + lane));
    int i = s;
    for (; i + 4 <= e; i += 4) {
        int s0 = g_col[i], s1 = g_col[i + 1], s2 = g_col[i + 2], s3 = g_col[i + 3];
        uint2 r0 = __ldg(((const uint2*)(g_hh + (size_t)s0 * D)) + lane);
        uint2 r1 = __ldg(((const uint2*)(g_hh + (size_t)s1 * D)) + lane);
        uint2 r2 = __ldg(((const uint2*)(g_hh + (size_t)s2 * D)) + lane);
        uint2 r3 = __ldg(((const uint2*)(g_hh + (size_t)s3 * D)) + lane);
        acc_h4(acc, r0); acc_h4(acc, r1); acc_h4(acc, r2); acc_h4(acc, r3);
    }
    for (; i < e; i++)
        acc_h4(acc, __ldg(((const uint2*)(g_hh + (size_t)g_col[i] * D)) + lane));
    uint2 pk;
    pk.x = pack_h2(acc.x, acc.y);
    pk.y = pack_h2(acc.z, acc.w);
    ((uint2*)(g_ah + (size_t)warp * D))[lane] = pk;
}

// ---- persistent fused GIN layer + GraphNorm apply -------------------------
// W1 and W2 stay resident in SMEM across the tile loop (layer-constant).
// smem = 3 x 128 x PADH halfs = 104.4KB -> exactly 2 CTAs/SM; with
// __launch_bounds__(512,2) all 296 CTAs are provably resident, so the
// software grid barrier is deadlock-free.
#define SMEM_GIN (3 * 128 * PADH * 2)

__global__ void __launch_bounds__(512, 2) k_gin(int layer,
                                                const float* __restrict__ bias1,
                                                const float* __restrict__ bias2,
                                                const void* __restrict__ batch,
                                                const float* __restrict__ gnw,
                                                const float* __restrict__ gnb,
                                                const float* __restrict__ gns,
                                                int last) {
    extern __shared__ __half smh[];
    __half* As  = smh;                    // [128][PADH] A / H1 / H staging
    __half* Bs1 = smh + 128 * PADH;       // [128][PADH] W1^T (resident)
    __half* Bs2 = smh + 2 * 128 * PADH;   // [128][PADH] W2^T (resident)
    uint32_t* As32  = (uint32_t*)As;
    uint32_t* Bs1_32 = (uint32_t*)Bs1;
    uint32_t* Bs2_32 = (uint32_t*)Bs2;
    __shared__ float b1s[128], b2s[128];
    __shared__ int gids[128];

    int tid = threadIdx.x, lane = tid & 31, wid = tid >> 5;
    int warp_m = wid & 3, warp_n = wid >> 2;     // 4 x 4 warp grid, 32x32 tiles
    int gID = lane >> 2, tig = lane & 3;

    // one-time: stage W1^T, W2^T, biases
#pragma unroll
    for (int it = 0; it < 4; it++) {
        int idx = tid + it * 512;
        int r = idx >> 4, c8 = (idx & 15) * 8;
        *(uint4*)(Bs1 + r * PADH + c8) = *(const uint4*)(g_wTh[layer] + r * D + c8);
        *(uint4*)(Bs2 + r * PADH + c8) = *(const uint4*)(g_wTh[4 + layer] + r * D + c8);
    }
    if (tid < 128) b1s[tid] = bias1[tid];
    else if (tid < 256) b2s[tid - 128] = bias2[tid - 128];
    __syncthreads();

    // ---------------- phase 1: GEMM tiles + stats ----------------
    for (int t = blockIdx.x; t < GIN_TILES; t += GIN_GRID) {
        int rb = t * 128;
        int nvalid = min(128, N_NODES - rb);

#pragma unroll
        for (int it = 0; it < 4; it++) {          // stage A
            int idx = tid + it * 512;
            int r = idx >> 4, c8 = (idx & 15) * 8;
            uint4 v = make_uint4(0, 0, 0, 0);
            if (r < nvalid)
                v = *(const uint4*)(g_ah + (size_t)(rb + r) * D + c8);
            *(uint4*)(As + r * PADH + c8) = v;
        }
        if (tid >= 256 && tid < 384) {
            int r = tid - 256;
            gids[r] = (r < nvalid) ? b_at(batch, rb + r) : 0;
        }
        __syncthreads();

        float c[2][4][4];
#pragma unroll
        for (int i = 0; i < 2; i++)
#pragma unroll
            for (int j = 0; j < 4; j++)
#pragma unroll
                for (int q = 0; q < 4; q++) c[i][j][q] = 0.f;

        // GEMM1 (As x Bs1)
#pragma unroll
        for (int kk = 0; kk < 8; kk++) {
            int kw = kk * 8 + tig;
            uint32_t a[2][4];
#pragma unroll
            for (int i = 0; i < 2; i++) {
                int r0 = (warp_m * 32 + i * 16 + gID) * 68;
                a[i][0] = As32[r0 + kw];
                a[i][1] = As32[r0 + 8 * 68 + kw];
                a[i][2] = As32[r0 + kw + 4];
                a[i][3] = As32[r0 + 8 * 68 + kw + 4];
            }
#pragma unroll
            for (int j = 0; j < 4; j++) {
                int n = warp_n * 32 + j * 8 + gID;
                uint32_t b0 = Bs1_32[n * 68 + kw];
                uint32_t b1 = Bs1_32[n * 68 + kw + 4];
                mma_f16(c[0][j], a[0][0], a[0][1], a[0][2], a[0][3], b0, b1);
                mma_f16(c[1][j], a[1][0], a[1][1], a[1][2], a[1][3], b0, b1);
            }
        }
        __syncthreads();

        // H1 (fp16) -> As
#pragma unroll
        for (int i = 0; i < 2; i++) {
            int r0 = warp_m * 32 + i * 16 + gID;
#pragma unroll
            for (int j = 0; j < 4; j++) {
                int cb = warp_n * 32 + j * 8 + 2 * tig;
                int w = warp_n * 16 + j * 4 + tig;
                As32[r0 * 68 + w] =
                    pack_h2(fmaxf(c[i][j][0] + b1s[cb], 0.f),
                            fmaxf(c[i][j][1] + b1s[cb + 1], 0.f));
                As32[(r0 + 8) * 68 + w] =
                    pack_h2(fmaxf(c[i][j][2] + b1s[cb], 0.f),
                            fmaxf(c[i][j][3] + b1s[cb + 1], 0.f));
            }
        }
        __syncthreads();

        // GEMM2 (As x Bs2)
#pragma unroll
        for (int i = 0; i < 2; i++)
#pragma unroll
            for (int j = 0; j < 4; j++)
#pragma unroll
                for (int q = 0; q < 4; q++) c[i][j][q] = 0.f;

#pragma unroll
        for (int kk = 0; kk < 8; kk++) {
            int kw = kk * 8 + tig;
            uint32_t a[2][4];
#pragma unroll
            for (int i = 0; i < 2; i++) {
                int r0 = (warp_m * 32 + i * 16 + gID) * 68;
                a[i][0] = As32[r0 + kw];
                a[i][1] = As32[r0 + 8 * 68 + kw];
                a[i][2] = As32[r0 + kw + 4];
                a[i][3] = As32[r0 + 8 * 68 + kw + 4];
            }
#pragma unroll
            for (int j = 0; j < 4; j++) {
                int n = warp_n * 32 + j * 8 + gID;
                uint32_t b0 = Bs2_32[n * 68 + kw];
                uint32_t b1 = Bs2_32[n * 68 + kw + 4];
                mma_f16(c[0][j], a[0][0], a[0][1], a[0][2], a[0][3], b0, b1);
                mma_f16(c[1][j], a[1][0], a[1][1], a[1][2], a[1][3], b0, b1);
            }
        }
        __syncthreads();   // GEMM2 As reads done before H staging overwrite

        // epilogue: H (fp16) -> g_h16 + As staging for stats
#pragma unroll
        for (int i = 0; i < 2; i++) {
            int lr0 = warp_m * 32 + i * 16 + gID;
            int lr1 = lr0 + 8;
#pragma unroll
            for (int j = 0; j < 4; j++) {
                int cb = warp_n * 32 + j * 8 + 2 * tig;
                int w = warp_n * 16 + j * 4 + tig;
                uint32_t p0 = pack_h2(fmaxf(c[i][j][0] + b2s[cb], 0.f),
                                      fmaxf(c[i][j][1] + b2s[cb + 1], 0.f));
                uint32_t p1 = pack_h2(fmaxf(c[i][j][2] + b2s[cb], 0.f),
                                      fmaxf(c[i][j][3] + b2s[cb + 1], 0.f));
                As32[lr0 * 68 + w] = p0;
                As32[lr1 * 68 + w] = p1;
                if (lr0 < nvalid)
                    *(uint32_t*)(g_h16 + (size_t)(rb + lr0) * D + cb) = p0;
                if (lr1 < nvalid)
                    *(uint32_t*)(g_h16 + (size_t)(rb + lr1) * D + cb) = p1;
            }
        }
        __syncthreads();

        // per-graph stats from fp16 staging (consistent with applied H)
        {
            int d = tid & 127, strip = tid >> 7;
            int r0 = strip * 32, r1 = min(r0 + 32, nvalid);
            if (r0 < nvalid) {
                int curg = gids[r0];
                float s = 0.f, q = 0.f;
                for (int r = r0; r < r1; r++) {
                    int g = gids[r];
                    if (g != curg) {
                        atomicAdd(&g_stat[layer][curg][0][d], s);
                        atomicAdd(&g_stat[layer][curg][1][d], q);
                        s = 0.f; q = 0.f; curg = g;
                    }
                    float v = __half2float(As[r * PADH + d]);
                    s += v; q += v * v;
                }
                atomicAdd(&g_stat[layer][curg][0][d], s);
                atomicAdd(&g_stat[layer][curg][1][d], q);
            }
        }
        __syncthreads();   // before next tile overwrites As
    }

    // ---------------- grid barrier (deadlock-free: all CTAs resident) ------
    __threadfence();
    __syncthreads();
    if (tid == 0) {
        atomicAdd(&g_bar[layer], 1);
        while (atomicAdd(&g_bar[layer], 0) < GIN_GRID)
            __nanosleep(64);
    }
    __syncthreads();
    __threadfence();

    // ---------------- phase 2: GraphNorm apply on own tiles ----------------
    for (int t = blockIdx.x; t < GIN_TILES; t += GIN_GRID) {
        int rb = t * 128;
        int nvalid = min(128, N_NODES - rb);
        for (int rr = wid; rr < nvalid; rr += 16) {
            int r = rb + rr;
            int g = b_at(batch, r);
            float cgc = g_gcnt[g];
            int d0 = lane * 4;
            uint2 hr = ((const uint2*)(g_h16 + (size_t)r * D))[lane];
            float2 hf0 = __half22float2(*reinterpret_cast<__half2*>(&hr.x));
            float2 hf1 = __half22float2(*reinterpret_cast<__half2*>(&hr.y));
            float4 h = make_float4(hf0.x, hf0.y, hf1.x, hf1.y);
            float4 s4 = *(const float4*)&g_stat[layer][g][0][d0];
            float4 q4 = *(const float4*)&g_stat[layer][g][1][d0];
            float4 ms4 = *(const float4*)(gns + layer * D + d0);
            float4 w4  = *(const float4*)(gnw + layer * D + d0);
            float4 b4  = *(const float4*)(gnb + layer * D + d0);
            float4 o;
#define GN1(X) {                                                   \
    float mean = s4.X / cgc;                                       \
    float aa = mean * ms4.X;                                       \
    float var = q4.X / cgc - 2.f * aa * mean + aa * aa;            \
    float rstd = rsqrtf(var + GN_EPS);                             \
    o.X = fmaxf(w4.X * (h.X - aa) * rstd + b4.X, 0.f); }
            GN1(x) GN1(y) GN1(z) GN1(w)
#undef GN1
            if (last) {
                atomicAdd(&g_pool[g * D + d0 + 0], o.x);
                atomicAdd(&g_pool[g * D + d0 + 1], o.y);
                atomicAdd(&g_pool[g * D + d0 + 2], o.z);
                atomicAdd(&g_pool[g * D + d0 + 3], o.w);
            } else {
                uint2 pk;
                pk.x = pack_h2(o.x, o.y);
                pk.y = pack_h2(o.z, o.w);
                ((uint2*)(g_hh + (size_t)r * D))[lane] = pk;
            }
        }
    }
}

// ------------------------- final MLP + log_softmax -------------------------
__global__ void __launch_bounds__(128) k_mlp(const float* __restrict__ fw1,
                                             const float* __restrict__ fb1,
                                             const float* __restrict__ fw2,
                                             const float* __restrict__ fb2,
                                             const float* __restrict__ fw3,
                                             const float* __restrict__ fb3,
                                             float* __restrict__ out) {
    int g = blockIdx.x, t = threadIdx.x;
    __shared__ float v[D], v2[D], o[C], red[2];
    v[t] = g_pool[g * D + t];
    __syncthreads();
    float acc = fb1[t];
    for (int k = 0; k < D; k++) acc += v[k] * fw1[k * D + t];
    v2[t] = fmaxf(acc, 0.f);
    __syncthreads();
    acc = fb2[t];
    for (int k = 0; k < D; k++) acc += v2[k] * fw2[k * D + t];
    __syncthreads();
    v[t] = fmaxf(acc, 0.f);
    __syncthreads();
    if (t < C) {
        float a = fb3[t];
        for (int k = 0; k < D; k++) a += v[k] * fw3[k * C + t];
        o[t] = a;
    }
    __syncthreads();
    if (t == 0) {
        float m = -1e30f;
        for (int cc = 0; cc < C; cc++) m = fmaxf(m, o[cc]);
        float se = 0.f;
        for (int cc = 0; cc < C; cc++) se += expf(o[cc] - m);
        red[0] = m; red[1] = logf(se);
    }
    __syncthreads();
    if (t < C) out[g * C + t] = o[t] - red[0] - red[1];
}

// ------------------------- launcher ----------------------------------------
extern "C" void kernel_launch(void* const* d_in, const int* in_sizes, int n_in,
                              void* d_out, int out_size) {
    const float* x    = (const float*)d_in[0];
    const float* w1   = (const float*)d_in[1];
    const float* b1   = (const float*)d_in[2];
    const float* w2   = (const float*)d_in[3];
    const float* b2   = (const float*)d_in[4];
    const float* gnw  = (const float*)d_in[5];
    const float* gnb  = (const float*)d_in[6];
    const float* gns  = (const float*)d_in[7];
    const float* fw1  = (const float*)d_in[8];
    const float* fb1  = (const float*)d_in[9];
    const float* fw2  = (const float*)d_in[10];
    const float* fb2  = (const float*)d_in[11];
    const float* fw3  = (const float*)d_in[12];
    const float* fb3  = (const float*)d_in[13];
    const void*  edge  = d_in[14];
    const void*  batch = d_in[15];
    float* out = (float*)d_out;

    cudaFuncSetAttribute(k_gin, cudaFuncAttributeMaxDynamicSharedMemorySize,
                         SMEM_GIN);

    // prologue: fused prep, then CSR build
    k_prep<<<1024, 256>>>((const int*)edge, (const int*)batch, w1, w2, x);
    k_hist<<<(N_EDGES + 255) / 256, 256>>>(edge);
    k_scan<<<NB_SCAN, 256>>>();
    k_fill<<<(N_EDGES + 255) / 256, 256>>>(edge);

    const int aggGrid = (N_NODES * 32 + 255) / 256;   // 6250

    for (int l = 0; l < L; l++) {
        k_agg<<<aggGrid, 256>>>();                    // read hh, write ah
        k_gin<<<GIN_GRID, 512, SMEM_GIN>>>(l,         // read ah, write hh/pool
                                           b1 + (size_t)l * D, b2 + (size_t)l * D,
                                           batch, gnw, gnb, gns, l == L - 1);
    }
    k_mlp<<<N_GRAPHS, 128>>>(fw1, fb1, fw2, fb2, fw3, fb3, out);
}

// round 16
// speedup vs baseline: 1.1303x; 1.0099x over previous
#include <cuda_runtime.h>
#include <cuda_fp16.h>
#include <cstdint>

#define N_NODES 50000
#define N_EDGES 800000
#define N_GRAPHS 128
#define D 128
#define L 4
#define C 10
#define GN_EPS 1e-5f
#define NB_SCAN 196
#define PAD 132          // float padding (stats staging)
#define PADH 136         // half padding (GEMM tiles), 68 words/row
#define ZERO_ELEMS (L * N_GRAPHS * 2 * D)
#define GIN_TILES 391    // ceil(N_NODES/128)
#define GIN_GRID 296     // 148 SMs x 2 guaranteed-resident CTAs

// ------------------------- device scratch (static, no allocs) -------------
__device__ __half g_h16[(size_t)N_NODES * D]; // un-normalized H (fp16)
__device__ __half g_ah[(size_t)N_NODES * D];  // agg output (fp16, gin input)
__device__ __half g_hh[(size_t)N_NODES * D];  // fp16 normalized state
__device__ int    g_rowptr[N_NODES + 1];
__device__ int    g_cursor[N_NODES];
__device__ int    g_cnt[N_NODES];
__device__ int    g_col[N_EDGES];
__device__ int    g_gptr[N_GRAPHS + 1];
__device__ float  g_gcnt[N_GRAPHS];
__device__ float  g_pool[N_GRAPHS * D];
__device__ float  g_stat[L][N_GRAPHS][2][D];
__device__ __half g_wTh[8][16384];            // W^T fp16, B[n][k]
__device__ int    g_bar[L];                   // grid barrier counters
__device__ int    g_is64e;
__device__ int    g_is64b;

// ------------------------- helpers ----------------------------------------
__device__ __forceinline__ int e_at(const void* p, long long i) {
    if (g_is64e) return (int)((const long long*)p)[i];
    return ((const int*)p)[i];
}
__device__ __forceinline__ int b_at(const void* p, long long i) {
    if (g_is64b) return (int)((const long long*)p)[i];
    return ((const int*)p)[i];
}

// mma.sync m16n8k16 fp16 (fp32 accum): C += A*B
__device__ __forceinline__ void mma_f16(float c[4], uint32_t a0, uint32_t a1,
                                        uint32_t a2, uint32_t a3,
                                        uint32_t b0, uint32_t b1) {
    asm volatile(
        "mma.sync.aligned.m16n8k16.row.col.f32.f16.f16.f32 "
        "{%0,%1,%2,%3}, {%4,%5,%6,%7}, {%8,%9}, {%0,%1,%2,%3};"
        : "+f"(c[0]), "+f"(c[1]), "+f"(c[2]), "+f"(c[3])
        : "r"(a0), "r"(a1), "r"(a2), "r"(a3), "r"(b0), "r"(b1));
}

__device__ __forceinline__ void acc_h4(float4& acc, uint2 r) {
    float2 f0 = __half22float2(*reinterpret_cast<__half2*>(&r.x));
    float2 f1 = __half22float2(*reinterpret_cast<__half2*>(&r.y));
    acc.x += f0.x; acc.y += f0.y; acc.z += f1.x; acc.w += f1.y;
}
__device__ __forceinline__ uint32_t pack_h2(float x, float y) {
    __half2 h = __floats2half2_rn(x, y);
    return *reinterpret_cast<uint32_t*>(&h);
}

// --------- fused prologue: zero + detect + graphs + wT + x mirror ----------
__global__ void k_prep(const int* __restrict__ ew, const int* __restrict__ bw,
                       const float* __restrict__ w1, const float* __restrict__ w2,
                       const float* __restrict__ x) {
    int gsz = gridDim.x * blockDim.x;
    int gid0 = blockIdx.x * blockDim.x + threadIdx.x;

    if (blockIdx.x == 0) {
        __shared__ int s_ez, s_bg;
        if (threadIdx.x == 0) { s_ez = 1; s_bg = 0; }
        __syncthreads();
        for (int j = threadIdx.x; j < 128; j += blockDim.x)
            if (ew[2 * j + 1] != 0) atomicAnd(&s_ez, 0);
        for (int j = threadIdx.x; j < 24999; j += blockDim.x)
            if (bw[2 * j] > bw[2 * j + 1]) atomicOr(&s_bg, 1);
        __syncthreads();
        if (threadIdx.x == 0) {
            g_is64e = s_ez; g_is64b = s_bg;
            for (int l = 0; l < L; l++) g_bar[l] = 0;
        }
        if (threadIdx.x < N_GRAPHS) {
            int g = threadIdx.x;
            int lo = 0, hi = N_NODES;
            while (lo < hi) {
                int mid = (lo + hi) >> 1;
                int v = s_bg ? (int)((const long long*)bw)[mid] : bw[mid];
                if (v < g) lo = mid + 1; else hi = mid;
            }
            g_gptr[g] = lo;
            if (g == 0) g_gptr[N_GRAPHS] = N_NODES;
        }
        __syncthreads();
        if (threadIdx.x < N_GRAPHS) {
            int g = threadIdx.x;
            int nxt = (g < N_GRAPHS - 1) ? g_gptr[g + 1] : N_NODES;
            g_gcnt[g] = fmaxf((float)(nxt - g_gptr[g]), 1.0f);
        }
    }

    for (int i = gid0; i < ZERO_ELEMS; i += gsz) {
        if (i < N_NODES) g_cnt[i] = 0;
        (&g_stat[0][0][0][0])[i] = 0.f;
        if (i < N_GRAPHS * D) g_pool[i] = 0.f;
    }
    for (int i = gid0; i < 8 * 16384; i += gsz) {
        int m = i >> 14, idx = i & 16383;
        int k = idx >> 7, n = idx & 127;
        const float* W = (m < 4) ? (w1 + (size_t)m * D * D)
                                 : (w2 + (size_t)(m - 4) * D * D);
        g_wTh[m][n * D + k] = __float2half(W[idx]);
    }
    for (int i = gid0; i < N_NODES * D / 4; i += gsz) {
        float4 v = *(const float4*)(x + (size_t)i * 4);
        uint2 pk;
        pk.x = pack_h2(v.x, v.y);
        pk.y = pack_h2(v.z, v.w);
        ((uint2*)g_hh)[i] = pk;
    }
}

// ------------------------- CSR build (ILP-4 edge kernels) ------------------
__global__ void k_hist(const void* __restrict__ e) {
    int i = (blockIdx.x * blockDim.x + threadIdx.x) * 4;
    if (i + 3 < N_EDGES) {
        int d0 = e_at(e, (long long)N_EDGES + i);
        int d1 = e_at(e, (long long)N_EDGES + i + 1);
        int d2 = e_at(e, (long long)N_EDGES + i + 2);
        int d3 = e_at(e, (long long)N_EDGES + i + 3);
        atomicAdd(&g_cnt[d0], 1);
        atomicAdd(&g_cnt[d1], 1);
        atomicAdd(&g_cnt[d2], 1);
        atomicAdd(&g_cnt[d3], 1);
    } else {
        for (int j = i; j < N_EDGES; j++)
            atomicAdd(&g_cnt[e_at(e, (long long)N_EDGES + j)], 1);
    }
}

__global__ void k_scan() {
    __shared__ int red[256];
    int t = threadIdx.x, b = blockIdx.x;
    int idx = b * 256 + t;

    int base = 0;
    for (int i = t; i < b * 256; i += 256) base += g_cnt[i];
    red[t] = base;
    __syncthreads();
    for (int off = 128; off > 0; off >>= 1) {
        if (t < off) red[t] += red[t + off];
        __syncthreads();
    }
    int blockBase = red[0];
    __syncthreads();

    int v = (idx < N_NODES) ? g_cnt[idx] : 0;
    red[t] = v;
    __syncthreads();
    for (int off = 1; off < 256; off <<= 1) {
        int u = (t >= off) ? red[t - off] : 0;
        __syncthreads(); red[t] += u; __syncthreads();
    }
    if (idx < N_NODES) {
        int rp = blockBase + red[t] - v;
        g_rowptr[idx] = rp; g_cursor[idx] = rp;
    }
    if (b == NB_SCAN - 1 && t == 255) g_rowptr[N_NODES] = blockBase + red[255];
}

__global__ void k_fill(const void* __restrict__ e) {
    int i = (blockIdx.x * blockDim.x + threadIdx.x) * 4;
    if (i + 3 < N_EDGES) {
        int s0 = e_at(e, i),     s1 = e_at(e, i + 1);
        int s2 = e_at(e, i + 2), s3 = e_at(e, i + 3);
        int d0 = e_at(e, (long long)N_EDGES + i);
        int d1 = e_at(e, (long long)N_EDGES + i + 1);
        int d2 = e_at(e, (long long)N_EDGES + i + 2);
        int d3 = e_at(e, (long long)N_EDGES + i + 3);
        int p0 = atomicAdd(&g_cursor[d0], 1);
        int p1 = atomicAdd(&g_cursor[d1], 1);
        int p2 = atomicAdd(&g_cursor[d2], 1);
        int p3 = atomicAdd(&g_cursor[d3], 1);
        g_col[p0] = s0; g_col[p1] = s1; g_col[p2] = s2; g_col[p3] = s3;
    } else {
        for (int j = i; j < N_EDGES; j++) {
            int s = e_at(e, j);
            int d = e_at(e, (long long)N_EDGES + j);
            g_col[atomicAdd(&g_cursor[d], 1)] = s;
        }
    }
}

// ------------------------- aggregation (fp16 in, fp16 out) -----------------
// Standalone high-parallelism gather (R14 lesson: do NOT fuse into gin).
__global__ void __launch_bounds__(256) k_agg() {
    int warp = (blockIdx.x * blockDim.x + threadIdx.x) >> 5;
    int lane = threadIdx.x & 31;
    if (warp >= N_NODES) return;
    int s = g_rowptr[warp], e = g_rowptr[warp + 1];
    float4 acc = make_float4(0.f, 0.f, 0.f, 0.f);
    acc_h4(acc, __ldg(((const uint2*)(g_hh + (size_t)warp * D)) + lane));
    int i = s;
    for (; i + 4 <= e; i += 4) {
        int s0 = g_col[i], s1 = g_col[i + 1], s2 = g_col[i + 2], s3 = g_col[i + 3];
        uint2 r0 = __ldg(((const uint2*)(g_hh + (size_t)s0 * D)) + lane);
        uint2 r1 = __ldg(((const uint2*)(g_hh + (size_t)s1 * D)) + lane);
        uint2 r2 = __ldg(((const uint2*)(g_hh + (size_t)s2 * D)) + lane);
        uint2 r3 = __ldg(((const uint2*)(g_hh + (size_t)s3 * D)) + lane);
        acc_h4(acc, r0); acc_h4(acc, r1); acc_h4(acc, r2); acc_h4(acc, r3);
    }
    for (; i < e; i++)
        acc_h4(acc, __ldg(((const uint2*)(g_hh + (size_t)g_col[i] * D)) + lane));
    uint2 pk;
    pk.x = pack_h2(acc.x, acc.y);
    pk.y = pack_h2(acc.z, acc.w);
    ((uint2*)(g_ah + (size_t)warp * D))[lane] = pk;
}

// ---- persistent fused GIN layer + GraphNorm apply (R13 config) ------------
// 296 CTAs, __launch_bounds__(512,2), smem 69.6KB => all resident => the
// software grid barrier is deadlock-free.
#define SMEM_GIN ((128 * PADH + 128 * PADH) * 2)

__global__ void __launch_bounds__(512, 2) k_gin(int layer,
                                                const float* __restrict__ bias1,
                                                const float* __restrict__ bias2,
                                                const void* __restrict__ batch,
                                                const float* __restrict__ gnw,
                                                const float* __restrict__ gnb,
                                                const float* __restrict__ gns,
                                                int last) {
    extern __shared__ __half smh[];
    __half* As = smh;                    // [128][PADH]
    __half* Bs = smh + 128 * PADH;       // [128][PADH]
    uint32_t* As32 = (uint32_t*)As;
    uint32_t* Bs32 = (uint32_t*)Bs;
    __shared__ float b1s[128], b2s[128];
    __shared__ int gids[128];

    int tid = threadIdx.x, lane = tid & 31, wid = tid >> 5;
    int warp_m = wid & 3, warp_n = wid >> 2;     // 4 x 4 warp grid, 32x32 tiles
    int gID = lane >> 2, tig = lane & 3;

    // ---------------- phase 1: GEMM tiles + stats ----------------
    for (int t = blockIdx.x; t < GIN_TILES; t += GIN_GRID) {
        int rb = t * 128;
        int nvalid = min(128, N_NODES - rb);

#pragma unroll
        for (int it = 0; it < 4; it++) {          // stage A
            int idx = tid + it * 512;
            int r = idx >> 4, c8 = (idx & 15) * 8;
            uint4 v = make_uint4(0, 0, 0, 0);
            if (r < nvalid)
                v = *(const uint4*)(g_ah + (size_t)(rb + r) * D + c8);
            *(uint4*)(As + r * PADH + c8) = v;
        }
#pragma unroll
        for (int it = 0; it < 4; it++) {          // stage W1^T
            int idx = tid + it * 512;
            int r = idx >> 4, c8 = (idx & 15) * 8;
            *(uint4*)(Bs + r * PADH + c8) = *(const uint4*)(g_wTh[layer] + r * D + c8);
        }
        if (tid < 128) b1s[tid] = bias1[tid];
        else if (tid < 256) b2s[tid - 128] = bias2[tid - 128];
        else if (tid < 384) {
            int r = tid - 256;
            gids[r] = (r < nvalid) ? b_at(batch, rb + r) : 0;
        }
        __syncthreads();

        float c[2][4][4];
#pragma unroll
        for (int i = 0; i < 2; i++)
#pragma unroll
            for (int j = 0; j < 4; j++)
#pragma unroll
                for (int q = 0; q < 4; q++) c[i][j][q] = 0.f;

        // GEMM1
#pragma unroll
        for (int kk = 0; kk < 8; kk++) {
            int kw = kk * 8 + tig;
            uint32_t a[2][4];
#pragma unroll
            for (int i = 0; i < 2; i++) {
                int r0 = (warp_m * 32 + i * 16 + gID) * 68;
                a[i][0] = As32[r0 + kw];
                a[i][1] = As32[r0 + 8 * 68 + kw];
                a[i][2] = As32[r0 + kw + 4];
                a[i][3] = As32[r0 + 8 * 68 + kw + 4];
            }
#pragma unroll
            for (int j = 0; j < 4; j++) {
                int n = warp_n * 32 + j * 8 + gID;
                uint32_t b0 = Bs32[n * 68 + kw];
                uint32_t b1 = Bs32[n * 68 + kw + 4];
                mma_f16(c[0][j], a[0][0], a[0][1], a[0][2], a[0][3], b0, b1);
                mma_f16(c[1][j], a[1][0], a[1][1], a[1][2], a[1][3], b0, b1);
            }
        }
        __syncthreads();

        // H1 -> As, stage W2^T -> Bs
#pragma unroll
        for (int i = 0; i < 2; i++) {
            int r0 = warp_m * 32 + i * 16 + gID;
#pragma unroll
            for (int j = 0; j < 4; j++) {
                int cb = warp_n * 32 + j * 8 + 2 * tig;
                int w = warp_n * 16 + j * 4 + tig;
                As32[r0 * 68 + w] =
                    pack_h2(fmaxf(c[i][j][0] + b1s[cb], 0.f),
                            fmaxf(c[i][j][1] + b1s[cb + 1], 0.f));
                As32[(r0 + 8) * 68 + w] =
                    pack_h2(fmaxf(c[i][j][2] + b1s[cb], 0.f),
                            fmaxf(c[i][j][3] + b1s[cb + 1], 0.f));
            }
        }
#pragma unroll
        for (int it = 0; it < 4; it++) {
            int idx = tid + it * 512;
            int r = idx >> 4, c8 = (idx & 15) * 8;
            *(uint4*)(Bs + r * PADH + c8) = *(const uint4*)(g_wTh[4 + layer] + r * D + c8);
        }
        __syncthreads();

        // GEMM2
#pragma unroll
        for (int i = 0; i < 2; i++)
#pragma unroll
            for (int j = 0; j < 4; j++)
#pragma unroll
                for (int q = 0; q < 4; q++) c[i][j][q] = 0.f;

#pragma unroll
        for (int kk = 0; kk < 8; kk++) {
            int kw = kk * 8 + tig;
            uint32_t a[2][4];
#pragma unroll
            for (int i = 0; i < 2; i++) {
                int r0 = (warp_m * 32 + i * 16 + gID) * 68;
                a[i][0] = As32[r0 + kw];
                a[i][1] = As32[r0 + 8 * 68 + kw];
                a[i][2] = As32[r0 + kw + 4];
                a[i][3] = As32[r0 + 8 * 68 + kw + 4];
            }
#pragma unroll
            for (int j = 0; j < 4; j++) {
                int n = warp_n * 32 + j * 8 + gID;
                uint32_t b0 = Bs32[n * 68 + kw];
                uint32_t b1 = Bs32[n * 68 + kw + 4];
                mma_f16(c[0][j], a[0][0], a[0][1], a[0][2], a[0][3], b0, b1);
                mma_f16(c[1][j], a[1][0], a[1][1], a[1][2], a[1][3], b0, b1);
            }
        }
        __syncthreads();

        // epilogue: H -> g_h16 + smem float staging for stats
        float* Hs = (float*)smh;
#pragma unroll
        for (int i = 0; i < 2; i++) {
            int lr0 = warp_m * 32 + i * 16 + gID;
            int lr1 = lr0 + 8;
#pragma unroll
            for (int j = 0; j < 4; j++) {
                int cb = warp_n * 32 + j * 8 + 2 * tig;
                float o00 = fmaxf(c[i][j][0] + b2s[cb], 0.f);
                float o01 = fmaxf(c[i][j][1] + b2s[cb + 1], 0.f);
                float o10 = fmaxf(c[i][j][2] + b2s[cb], 0.f);
                float o11 = fmaxf(c[i][j][3] + b2s[cb + 1], 0.f);
                Hs[lr0 * PAD + cb] = o00;  Hs[lr0 * PAD + cb + 1] = o01;
                Hs[lr1 * PAD + cb] = o10;  Hs[lr1 * PAD + cb + 1] = o11;
                if (lr0 < nvalid)
                    *(uint32_t*)(g_h16 + (size_t)(rb + lr0) * D + cb) = pack_h2(o00, o01);
                if (lr1 < nvalid)
                    *(uint32_t*)(g_h16 + (size_t)(rb + lr1) * D + cb) = pack_h2(o10, o11);
            }
        }
        __syncthreads();

        // per-graph stats
        {
            int d = tid & 127, strip = tid >> 7;
            int r0 = strip * 32, r1 = min(r0 + 32, nvalid);
            if (r0 < nvalid) {
                int curg = gids[r0];
                float s = 0.f, q = 0.f;
                for (int r = r0; r < r1; r++) {
                    int g = gids[r];
                    if (g != curg) {
                        atomicAdd(&g_stat[layer][curg][0][d], s);
                        atomicAdd(&g_stat[layer][curg][1][d], q);
                        s = 0.f; q = 0.f; curg = g;
                    }
                    float v = Hs[r * PAD + d];
                    s += v; q += v * v;
                }
                atomicAdd(&g_stat[layer][curg][0][d], s);
                atomicAdd(&g_stat[layer][curg][1][d], q);
            }
        }
        __syncthreads();   // before next tile overwrites smem
    }

    // ---------------- grid barrier (deadlock-free: all CTAs resident) ------
    __threadfence();
    __syncthreads();
    if (tid == 0) {
        atomicAdd(&g_bar[layer], 1);
        while (atomicAdd(&g_bar[layer], 0) < GIN_GRID)
            __nanosleep(64);
    }
    __syncthreads();
    __threadfence();

    // ---------------- phase 2: GraphNorm apply on own tiles ----------------
    for (int t = blockIdx.x; t < GIN_TILES; t += GIN_GRID) {
        int rb = t * 128;
        int nvalid = min(128, N_NODES - rb);
        for (int rr = wid; rr < nvalid; rr += 16) {
            int r = rb + rr;
            int g = b_at(batch, r);
            float cgc = g_gcnt[g];
            int d0 = lane * 4;
            uint2 hr = ((const uint2*)(g_h16 + (size_t)r * D))[lane];
            float2 hf0 = __half22float2(*reinterpret_cast<__half2*>(&hr.x));
            float2 hf1 = __half22float2(*reinterpret_cast<__half2*>(&hr.y));
            float4 h = make_float4(hf0.x, hf0.y, hf1.x, hf1.y);
            float4 s4 = *(const float4*)&g_stat[layer][g][0][d0];
            float4 q4 = *(const float4*)&g_stat[layer][g][1][d0];
            float4 ms4 = *(const float4*)(gns + layer * D + d0);
            float4 w4  = *(const float4*)(gnw + layer * D + d0);
            float4 b4  = *(const float4*)(gnb + layer * D + d0);
            float4 o;
#define GN1(X) {                                                   \
    float mean = s4.X / cgc;                                       \
    float aa = mean * ms4.X;                                       \
    float var = q4.X / cgc - 2.f * aa * mean + aa * aa;            \
    float rstd = rsqrtf(var + GN_EPS);                             \
    o.X = fmaxf(w4.X * (h.X - aa) * rstd + b4.X, 0.f); }
            GN1(x) GN1(y) GN1(z) GN1(w)
#undef GN1
            if (last) {
                atomicAdd(&g_pool[g * D + d0 + 0], o.x);
                atomicAdd(&g_pool[g * D + d0 + 1], o.y);
                atomicAdd(&g_pool[g * D + d0 + 2], o.z);
                atomicAdd(&g_pool[g * D + d0 + 3], o.w);
            } else {
                uint2 pk;
                pk.x = pack_h2(o.x, o.y);
                pk.y = pack_h2(o.z, o.w);
                ((uint2*)(g_hh + (size_t)r * D))[lane] = pk;
            }
        }
    }
}

// ------------------------- final MLP + log_softmax -------------------------
__global__ void __launch_bounds__(128) k_mlp(const float* __restrict__ fw1,
                                             const float* __restrict__ fb1,
                                             const float* __restrict__ fw2,
                                             const float* __restrict__ fb2,
                                             const float* __restrict__ fw3,
                                             const float* __restrict__ fb3,
                                             float* __restrict__ out) {
    int g = blockIdx.x, t = threadIdx.x;
    __shared__ float v[D], v2[D], o[C], red[2];
    v[t] = g_pool[g * D + t];
    __syncthreads();
    float acc = fb1[t];
    for (int k = 0; k < D; k++) acc += v[k] * fw1[k * D + t];
    v2[t] = fmaxf(acc, 0.f);
    __syncthreads();
    acc = fb2[t];
    for (int k = 0; k < D; k++) acc += v2[k] * fw2[k * D + t];
    __syncthreads();
    v[t] = fmaxf(acc, 0.f);
    __syncthreads();
    if (t < C) {
        float a = fb3[t];
        for (int k = 0; k < D; k++) a += v[k] * fw3[k * C + t];
        o[t] = a;
    }
    __syncthreads();
    if (t == 0) {
        float m = -1e30f;
        for (int cc = 0; cc < C; cc++) m = fmaxf(m, o[cc]);
        float se = 0.f;
        for (int cc = 0; cc < C; cc++) se += expf(o[cc] - m);
        red[0] = m; red[1] = logf(se);
    }
    __syncthreads();
    if (t < C) out[g * C + t] = o[t] - red[0] - red[1];
}

// ------------------------- launcher ----------------------------------------
extern "C" void kernel_launch(void* const* d_in, const int* in_sizes, int n_in,
                              void* d_out, int out_size) {
    const float* x    = (const float*)d_in[0];
    const float* w1   = (const float*)d_in[1];
    const float* b1   = (const float*)d_in[2];
    const float* w2   = (const float*)d_in[3];
    const float* b2   = (const float*)d_in[4];
    const float* gnw  = (const float*)d_in[5];
    const float* gnb  = (const float*)d_in[6];
    const float* gns  = (const float*)d_in[7];
    const float* fw1  = (const float*)d_in[8];
    const float* fb1  = (const float*)d_in[9];
    const float* fw2  = (const float*)d_in[10];
    const float* fb2  = (const float*)d_in[11];
    const float* fw3  = (const float*)d_in[12];
    const float* fb3  = (const float*)d_in[13];
    const void*  edge  = d_in[14];
    const void*  batch = d_in[15];
    float* out = (float*)d_out;

    cudaFuncSetAttribute(k_gin, cudaFuncAttributeMaxDynamicSharedMemorySize,
                         SMEM_GIN);

    // prologue: fused prep, then CSR build (ILP-4 edge kernels)
    k_prep<<<1024, 256>>>((const int*)edge, (const int*)batch, w1, w2, x);
    k_hist<<<(N_EDGES / 4 + 255) / 256, 256>>>(edge);
    k_scan<<<NB_SCAN, 256>>>();
    k_fill<<<(N_EDGES / 4 + 255) / 256, 256>>>(edge);

    const int aggGrid = (N_NODES * 32 + 255) / 256;   // 6250

    for (int l = 0; l < L; l++) {
        k_agg<<<aggGrid, 256>>>();                    // read hh, write ah
        k_gin<<<GIN_GRID, 512, SMEM_GIN>>>(l,         // read ah, write hh/pool
                                           b1 + (size_t)l * D, b2 + (size_t)l * D,
                                           batch, gnw, gnb, gns, l == L - 1);
    }
    k_mlp<<<N_GRAPHS, 128>>>(fw1, fb1, fw2, fb2, fw3, fb3, out);
}